// round 6
// baseline (speedup 1.0000x reference)
#include <cuda_runtime.h>
#include <cstddef>

#define N_ROWS 32768
#define DIMS   64
#define RULES  32
#define JLEN   65            // 1 + DIMS
#define EPSV   1e-12f
#define WARPS  8
#define RPW    4             // rows per warp
#define ROWS_PER_BLOCK (WARPS * RPW)   // 32
#define FULL   0xffffffffu

__global__ __launch_bounds__(256) void tsk_kernel(
    const float* __restrict__ Xz,
    const float* __restrict__ centers,
    const float* __restrict__ sigmas,
    const float* __restrict__ theta,
    float* __restrict__ out)
{
    // (inv_sigma, -center*inv_sigma) at float2 stride 65: conflict-free for lane=r
    __shared__ float2 s_pc[RULES * JLEN];
    __shared__ float  s_th[RULES * JLEN];

    const int tid  = threadIdx.x;
    const int warp = tid >> 5;
    const int lane = tid & 31;

    // ---- preprocess parameters into shared (once per block) ----
    for (int i = tid; i < RULES * DIMS; i += 256) {
        int r = i >> 6;           // i / 64
        int d = i & 63;
        float s   = sigmas[i];
        float inv = 1.0f / (s + EPSV);
        s_pc[r * JLEN + d] = make_float2(inv, -centers[i] * inv);
    }
    for (int i = tid; i < RULES * JLEN; i += 256) {
        s_th[i] = theta[i];       // theta is (R, 65) row-major
    }
    __syncthreads();

    float* __restrict__ y_out   = out;
    float* __restrict__ w_out   = out + N_ROWS;
    float* __restrict__ phi_out = out + N_ROWS + (size_t)N_ROWS * RULES;

    const int base = blockIdx.x * ROWS_PER_BLOCK + warp * RPW;

    // ---- x for 4 rows lives entirely in registers ----
    float xa[RPW], xb[RPW];
    #pragma unroll
    for (int k = 0; k < RPW; k++) {
        int row = base + k;
        xa[k] = Xz[row * DIMS + lane];
        xb[k] = Xz[row * DIMS + 32 + lane];
    }

    // ---- lane = rule: distance accumulation + theta dot, 4 rows at once ----
    float acc[RPW], dot[RPW];
    #pragma unroll
    for (int k = 0; k < RPW; k++) {
        acc[k] = 0.0f;
        dot[k] = s_th[lane * JLEN];    // bias theta[r][0]
    }

    #pragma unroll 8
    for (int d = 0; d < DIMS; d++) {
        float2 p = s_pc[lane * JLEN + d];          // (inv, -c*inv)
        float  t = s_th[lane * JLEN + d + 1];
        #pragma unroll
        for (int k = 0; k < RPW; k++) {
            // d is uniform -> compile-time register select, 1 shfl
            float xd = __shfl_sync(FULL, (d < 32) ? xa[k] : xb[k], d & 31);
            float z  = fmaf(xd, p.x, p.y);         // (x - c) * inv
            acc[k] = fmaf(z, z, acc[k]);
            dot[k] = fmaf(t, xd, dot[k]);
        }
    }

    // ---- softmax over rules (lanes) + y reduction + w writeback ----
    float wk[RPW];
    #pragma unroll
    for (int k = 0; k < RPW; k++) {
        float lw = -0.5f * acc[k];
        float m = lw;
        #pragma unroll
        for (int o = 16; o > 0; o >>= 1)
            m = fmaxf(m, __shfl_xor_sync(FULL, m, o));
        float e = __expf(lw - m);
        float s = e;
        #pragma unroll
        for (int o = 16; o > 0; o >>= 1)
            s += __shfl_xor_sync(FULL, s, o);
        float wv = e * (1.0f / (s + EPSV));
        wk[k] = wv;

        int row = base + k;
        w_out[(size_t)row * RULES + lane] = wv;    // coalesced 128B per row

        float yv = wv * dot[k];
        #pragma unroll
        for (int o = 16; o > 0; o >>= 1)
            yv += __shfl_xor_sync(FULL, yv, o);
        if (lane == 0) y_out[row] = yv;
    }

    // ---- Phi: per-rule register-direct stores, WRITE-BACK (no streaming hint).
    // Graph replays rewrite the same 277MB; normal stores let up to ~126MB stay
    // dirty-resident in L2 so subsequent replays write-hit and skip DRAM.
    #pragma unroll
    for (int k = 0; k < RPW; k++) {
        int row = base + k;
        float* __restrict__ ph = phi_out + (size_t)row * (RULES * JLEN);
        const float xak = xa[k];
        const float xbk = xb[k];
        const float wkk = wk[k];

        #pragma unroll
        for (int r = 0; r < RULES; r++) {
            float w = __shfl_sync(FULL, wkk, r);   // immediate lane index
            float* __restrict__ p = ph + r * JLEN;
            if (lane == 0) p[0] = w;
            p[1 + lane]  = w * xak;
            p[33 + lane] = w * xbk;
        }
    }
}

extern "C" void kernel_launch(void* const* d_in, const int* in_sizes, int n_in,
                              void* d_out, int out_size)
{
    const float* Xz      = (const float*)d_in[0];
    const float* centers = (const float*)d_in[1];
    const float* sigmas  = (const float*)d_in[2];
    const float* theta   = (const float*)d_in[3];
    float* out = (float*)d_out;

    tsk_kernel<<<N_ROWS / ROWS_PER_BLOCK, 256>>>(Xz, centers, sigmas, theta, out);
}

// round 8
// speedup vs baseline: 1.1044x; 1.1044x over previous
#include <cuda_runtime.h>
#include <cstddef>

#define N_ROWS 32768
#define DIMS   64
#define RULES  32
#define JLEN   65            // 1 + DIMS
#define EPSV   1e-12f
#define WARPS  8
#define RPW    4             // rows per warp
#define ROWS_PER_BLOCK (WARPS * RPW)   // 32
#define FULL   0xffffffffu

__global__ __launch_bounds__(256) void tsk_kernel(
    const float* __restrict__ Xz,
    const float* __restrict__ centers,
    const float* __restrict__ sigmas,
    const float* __restrict__ theta,
    float* __restrict__ out)
{
    // params packed as float4 pairs; strides 33/17 float4 => start bank 4*r,
    // conflict-free for lane=rule LDS.128 reads
    __shared__ float4 s_pc4[RULES * 33];   // (inv0, -c0*inv0, inv1, -c1*inv1) per d-pair
    __shared__ float4 s_thv[RULES * 17];   // theta[r][1+4t .. 4+4t]
    __shared__ float  s_thb[RULES];        // theta[r][0]

    const int tid  = threadIdx.x;
    const int warp = tid >> 5;
    const int lane = tid & 31;

    // ---- preprocess parameters into shared (once per block) ----
    for (int i = tid; i < RULES * 32; i += 256) {
        int r = i >> 5, dp = i & 31;
        int gi = r * DIMS + 2 * dp;
        float i0 = 1.0f / (sigmas[gi]     + EPSV);
        float i1 = 1.0f / (sigmas[gi + 1] + EPSV);
        s_pc4[r * 33 + dp] = make_float4(i0, -centers[gi] * i0,
                                         i1, -centers[gi + 1] * i1);
    }
    for (int i = tid; i < RULES * 16; i += 256) {
        int r = i >> 4, t = i & 15;
        const float* tp = theta + r * JLEN + 1 + 4 * t;
        s_thv[r * 17 + t] = make_float4(tp[0], tp[1], tp[2], tp[3]);
    }
    if (tid < RULES) s_thb[tid] = theta[tid * JLEN];
    __syncthreads();

    float* __restrict__ y_out   = out;
    float* __restrict__ w_out   = out + N_ROWS;
    float* __restrict__ phi_out = out + N_ROWS + (size_t)N_ROWS * RULES;

    const int base = blockIdx.x * ROWS_PER_BLOCK + warp * RPW;

    // ---- x for 4 rows in registers: lane holds (x[2l], x[2l+1]) ----
    float xe[RPW], xo[RPW];
    #pragma unroll
    for (int k = 0; k < RPW; k++) {
        int row = base + k;
        float2 xv = *reinterpret_cast<const float2*>(Xz + row * DIMS + 2 * lane);
        xe[k] = xv.x;
        xo[k] = xv.y;
    }

    // ---- lane = rule: distance accumulation + theta dot, 4 d's per iter ----
    float acc[RPW], dot[RPW];
    #pragma unroll
    for (int k = 0; k < RPW; k++) {
        acc[k] = 0.0f;
        dot[k] = s_thb[lane];
    }

    #pragma unroll
    for (int dq = 0; dq < 16; dq++) {
        float4 p0 = s_pc4[lane * 33 + 2 * dq];       // d = 4dq, 4dq+1
        float4 p1 = s_pc4[lane * 33 + 2 * dq + 1];   // d = 4dq+2, 4dq+3
        float4 t4 = s_thv[lane * 17 + dq];
        #pragma unroll
        for (int k = 0; k < RPW; k++) {
            float x0 = __shfl_sync(FULL, xe[k], 2 * dq);
            float x1 = __shfl_sync(FULL, xo[k], 2 * dq);
            float x2 = __shfl_sync(FULL, xe[k], 2 * dq + 1);
            float x3 = __shfl_sync(FULL, xo[k], 2 * dq + 1);
            float z0 = fmaf(x0, p0.x, p0.y);
            float z1 = fmaf(x1, p0.z, p0.w);
            float z2 = fmaf(x2, p1.x, p1.y);
            float z3 = fmaf(x3, p1.z, p1.w);
            acc[k] = fmaf(z0, z0, fmaf(z1, z1, fmaf(z2, z2, fmaf(z3, z3, acc[k]))));
            dot[k] = fmaf(t4.x, x0, fmaf(t4.y, x1, fmaf(t4.z, x2, fmaf(t4.w, x3, dot[k]))));
        }
    }

    // ---- softmax over rules (lanes) + y reduction + w writeback ----
    float wk[RPW];
    #pragma unroll
    for (int k = 0; k < RPW; k++) {
        float lw = -0.5f * acc[k];
        float m = lw;
        #pragma unroll
        for (int o = 16; o > 0; o >>= 1)
            m = fmaxf(m, __shfl_xor_sync(FULL, m, o));
        float e = __expf(lw - m);
        float s = e;
        #pragma unroll
        for (int o = 16; o > 0; o >>= 1)
            s += __shfl_xor_sync(FULL, s, o);
        float wv = e * (1.0f / (s + EPSV));
        wk[k] = wv;

        int row = base + k;
        w_out[(size_t)row * RULES + lane] = wv;    // coalesced 128B per row

        float yv = wv * dot[k];
        #pragma unroll
        for (int o = 16; o > 0; o >>= 1)
            yv += __shfl_xor_sync(FULL, yv, o);
        if (lane == 0) y_out[row] = yv;
    }

    // ---- Phi: parity-aligned STG.64 scheme ----
    // Segment r (65 floats at offset 65r): parity of 65r+s == parity of r+s.
    // even r: lane l stores float2 {w*x1[2l], w*x1[2l+1]} at 65r+2l   (covers s=0..63)
    // odd  r: lane l stores float2 {w*x1[2l+1], w*x1[2l+2]} at 65r+1+2l (covers s=1..64)
    // seams (even r): {w_r*x1[64], w_{r+1}} at 65r+64 — one scattered STG.64, 16 lanes.
    #pragma unroll
    for (int k = 0; k < RPW; k++) {
        int row = base + k;
        float* __restrict__ ph = phi_out + (size_t)row * (RULES * JLEN);
        const float wkk = wk[k];
        const float xek = xe[k];            // x[2l]   == x1[2l+1]
        const float xok = xo[k];            // x[2l+1] == x1[2l+2]
        float xm1 = __shfl_up_sync(FULL, xok, 1);          // x[2l-1] == x1[2l]
        float ae  = (lane == 0) ? 1.0f : xm1;              // x1[2l] incl. x1[0]=1
        float x63 = __shfl_sync(FULL, xok, 31);            // x1[64]

        #pragma unroll
        for (int r = 0; r < RULES; r++) {
            float w = __shfl_sync(FULL, wkk, r);
            if ((r & 1) == 0) {
                __stcs(reinterpret_cast<float2*>(ph + r * JLEN + 2 * lane),
                       make_float2(w * ae, w * xek));
            } else {
                __stcs(reinterpret_cast<float2*>(ph + r * JLEN + 1 + 2 * lane),
                       make_float2(w * xek, w * xok));
            }
        }

        // seams: full-warp shuffles, predicated store
        float w0 = __shfl_sync(FULL, wkk, (2 * lane) & 31);
        float w1 = __shfl_sync(FULL, wkk, (2 * lane + 1) & 31);
        if (lane < 16) {
            int r = 2 * lane;
            __stcs(reinterpret_cast<float2*>(ph + r * JLEN + 64),
                   make_float2(w0 * x63, w1));
        }
    }
}

extern "C" void kernel_launch(void* const* d_in, const int* in_sizes, int n_in,
                              void* d_out, int out_size)
{
    const float* Xz      = (const float*)d_in[0];
    const float* centers = (const float*)d_in[1];
    const float* sigmas  = (const float*)d_in[2];
    const float* theta   = (const float*)d_in[3];
    float* out = (float*)d_out;

    tsk_kernel<<<N_ROWS / ROWS_PER_BLOCK, 256>>>(Xz, centers, sigmas, theta, out);
}